// round 11
// baseline (speedup 1.0000x reference)
#include <cuda_runtime.h>
#include <cstdint>

// Problem constants: B=2, N=65536, M=8192, K=32
// TOTAL_GIBS=64 (16 cy, 16 cone, 16 disk, 16 ellip), NUM_OBSERVERS=16
#define EPSV 1e-8f
#define LOG2E_F 1.4426950408889634f

constexpr int Bc = 2;
constexpr int Nc = 65536;
constexpr int Mc = 8192;
constexpr int Kc = 32;
constexpr int NQ = Bc * Mc;                 // 16384 queries
constexpr int WARPS_PER_BLOCK = 8;
constexpr int THREADS = WARPS_PER_BLOCK * 32;
constexpr int Q_PER_WARP = 2;
constexpr int Q_PER_BLOCK = WARPS_PER_BLOCK * Q_PER_WARP;   // 16
constexpr int GRID_BLOCKS = NQ / Q_PER_BLOCK;               // 1024
constexpr int RPAD = 68;                    // meanS row stride (words)

typedef unsigned long long u64;

__device__ __forceinline__ float ex2f(float x) {
    float r; asm("ex2.approx.ftz.f32 %0, %1;" : "=f"(r) : "f"(x)); return r;
}
__device__ __forceinline__ float sqrtaf(float x) {
    float r; asm("sqrt.approx.ftz.f32 %0, %1;" : "=f"(r) : "f"(x)); return r;
}
// packed f32x2 ops (Blackwell): operate on aligned 64-bit register pairs
__device__ __forceinline__ u64 pk2(float lo, float hi) {
    u64 r; asm("mov.b64 %0, {%1, %2};" : "=l"(r) : "f"(lo), "f"(hi)); return r;
}
__device__ __forceinline__ u64 fma2(u64 a, u64 b, u64 c) {
    u64 d; asm("fma.rn.f32x2 %0, %1, %2, %3;" : "=l"(d) : "l"(a), "l"(b), "l"(c)); return d;
}
__device__ __forceinline__ u64 mul2(u64 a, u64 b) {
    u64 d; asm("mul.rn.f32x2 %0, %1, %2;" : "=l"(d) : "l"(a), "l"(b)); return d;
}
// acc += ex2(lo(v)) + ex2(hi(v))
__device__ __forceinline__ void ex2acc(u64 v, float& acc) {
    float a, b;
    asm("mov.b64 {%0, %1}, %2;" : "=f"(a), "=f"(b) : "l"(v));
    acc += ex2f(a);
    acc += ex2f(b);
}

// SoA monomial arrays per (warp, query); 16B aligned, immediate-offset friendly
struct __align__(16) QArr {
    float r4[Kc];    // off   0
    float r2[Kc];    // off 128
    float srz[Kc];   // off 256
    float rz2[Kc];   // off 384
    float rx2[Kc];   // off 512
};                   // 640 B

__global__ __launch_bounds__(THREADS, 5)
void gib_kernel(const float* __restrict__ points,
                const float* __restrict__ q_coords,
                const int*   __restrict__ support_idxs,
                const float* __restrict__ cy_p,
                const float* __restrict__ cone_p,
                const float* __restrict__ disk_p,
                const float* __restrict__ ellip_p,
                const float* __restrict__ lambdas,
                float* __restrict__ out)
{
    __shared__ QArr  sQ[WARPS_PER_BLOCK][Q_PER_WARP];              // 10 KB
    __shared__ float4 lamT4[256];                                  //  4 KB
    __shared__ __align__(16) float meanS[Q_PER_BLOCK * RPAD];      //  4.3 KB

    const int tid   = threadIdx.x;
    const int lane  = tid & 31;
    const int wslot = tid >> 5;
    const int qbase = blockIdx.x * Q_PER_BLOCK;
    const int qA    = qbase + wslot * 2;

    // ---- cooperative packed-transposed lambda load (once per block) ----
    {
        const float invK = 1.f / (float)Kc;
        int g4 = tid >> 4;          // 0..15
        int j  = tid & 15;          // 0..15
        float4 v;
        v.x = lambdas[(4 * g4 + 0) * 16 + j] * invK;
        v.y = lambdas[(4 * g4 + 1) * 16 + j] * invK;
        v.z = lambdas[(4 * g4 + 2) * 16 + j] * invK;
        v.w = lambdas[(4 * g4 + 3) * 16 + j] * invK;
        lamT4[g4 * 16 + j] = v;
    }

    // ---- per-lane gib constants (monomial affine forms, packed) ----
    // quad (g0=lane):   arg0 = c1*m1 + c2*m2 + c3*rz2 + c0
    //   lane<16  cyl : m1=r4, m2=r2 ; c1=-inv, c2=2a^2*inv, c3=0,      c0=-a^4*inv
    //   lane>=16 cone: m1=r2, m2=srz; c1=-inv, c2=2a*inv,   c3=-a^2inv, c0=-eps*inv
    // lin  (g1=l+32):   arg1 = e1*rx2 + e2*r2 + e3*rz2
    float c0, c1, c2, c3, e1, e2, e3;
    if (lane < 16) {
        float a  = cy_p[lane * 2 + 0];
        float sg = cy_p[lane * 2 + 1];
        float inv = LOG2E_F / (2.f * sg * sg + EPSV);
        float a2 = a * a;
        c1 = -inv; c2 = 2.f * a2 * inv; c3 = 0.f; c0 = -a2 * a2 * inv;
        float d0 = disk_p[lane * 2 + 0];
        float d1 = disk_p[lane * 2 + 1];
        e1 = 0.f;
        e2 = -LOG2E_F / (d0 * d0 + EPSV);
        e3 = -LOG2E_F / (d1 * d1 + EPSV);
    } else {
        int j = lane - 16;
        float a  = cone_p[j * 2 + 0];
        float sg = cone_p[j * 2 + 1];
        float inv = LOG2E_F / (2.f * sg * sg + EPSV);
        c1 = -inv; c2 = 2.f * a * inv; c3 = -a * a * inv; c0 = -EPSV * inv;
        float x0 = ellip_p[j * 3 + 0];
        float x1 = ellip_p[j * 3 + 1];
        float x2 = ellip_p[j * 3 + 2];
        float qx = -LOG2E_F / (x0 * x0 + EPSV);
        float qy = -LOG2E_F / (x1 * x1 + EPSV);
        e1 = qx - qy;
        e2 = qy;
        e3 = -LOG2E_F / (x2 * x2 + EPSV);
    }
    const u64 C0 = pk2(c0, c0), C1 = pk2(c1, c1), C2 = pk2(c2, c2), C3 = pk2(c3, c3);
    const u64 E1 = pk2(e1, e1), E2 = pk2(e2, e2), E3 = pk2(e3, e3);

    // ---- gather: lane k loads support point k for both queries ----
    #pragma unroll
    for (int qq = 0; qq < Q_PER_WARP; qq++) {
        int q = qA + qq;
        const float* qc = q_coords + q * 3;
        float qx = __ldg(qc + 0);
        float qy = __ldg(qc + 1);
        float qz = __ldg(qc + 2);
        int   idx = __ldg(support_idxs + q * Kc + lane);
        int   b   = q >> 13;                          // q / Mc
        unsigned pidx = ((unsigned)b << 16) + (unsigned)idx;   // b*Nc + idx
        unsigned offb = pidx * 12u;                   // parity select on idx&1
        const char* pb = (const char*)points + (offb & ~7u);
        float2 lo = __ldg((const float2*)pb);
        float2 hi = __ldg((const float2*)(pb + 8));
        bool odd = (idx & 1);
        float px = odd ? lo.y : lo.x;
        float py = odd ? hi.x : lo.y;
        float pz = odd ? hi.y : hi.x;
        float rx = px - qx;
        float ry = py - qy;
        float rz = pz - qz;
        float rx2 = rx * rx;
        float r2  = fmaf(ry, ry, rx2);
        float s   = sqrtaf(r2 + EPSV);
        QArr& A = sQ[wslot][qq];
        A.r4 [lane] = r2 * r2;
        A.r2 [lane] = r2;
        A.srz[lane] = s * rz;
        A.rz2[lane] = rz * rz;
        A.rx2[lane] = rx2;
    }
    __syncwarp();

    // lane-dependent monomial bases: m1 = r4|r2 , m2 = r2|srz
    const QArr& A0 = sQ[wslot][0];
    const QArr& A1 = sQ[wslot][1];
    const ulonglong2* m1A = (const ulonglong2*)(lane < 16 ? A0.r4 : A0.r2);
    const ulonglong2* m2A = (const ulonglong2*)(lane < 16 ? A0.r2 : A0.srz);
    const ulonglong2* rzA = (const ulonglong2*)A0.rz2;
    const ulonglong2* rxA = (const ulonglong2*)A0.rx2;
    const ulonglong2* r2A = (const ulonglong2*)A0.r2;
    const ulonglong2* m1B = (const ulonglong2*)(lane < 16 ? A1.r4 : A1.r2);
    const ulonglong2* m2B = (const ulonglong2*)(lane < 16 ? A1.r2 : A1.srz);
    const ulonglong2* rzB = (const ulonglong2*)A1.rz2;
    const ulonglong2* rxB = (const ulonglong2*)A1.rx2;
    const ulonglong2* r2B = (const ulonglong2*)A1.r2;

    float acc0A = 0.f, acc1A = 0.f, acc0B = 0.f, acc1B = 0.f;
    #pragma unroll 2
    for (int pp = 0; pp < Kc / 4; pp++) {      // 4 k-values per iteration
        // query A
        {
            ulonglong2 M1 = m1A[pp];           // (k0,k1),(k2,k3) packed pairs
            ulonglong2 M2 = m2A[pp];
            ulonglong2 Z  = rzA[pp];
            ulonglong2 X  = rxA[pp];
            ulonglong2 R  = r2A[pp];
            u64 t0 = fma2(C1, M1.x, fma2(C2, M2.x, fma2(C3, Z.x, C0)));
            u64 u0 = fma2(E1, X.x,  fma2(E2, R.x,  mul2(E3, Z.x)));
            u64 t1 = fma2(C1, M1.y, fma2(C2, M2.y, fma2(C3, Z.y, C0)));
            u64 u1 = fma2(E1, X.y,  fma2(E2, R.y,  mul2(E3, Z.y)));
            ex2acc(t0, acc0A); ex2acc(t1, acc0A);
            ex2acc(u0, acc1A); ex2acc(u1, acc1A);
        }
        // query B
        {
            ulonglong2 M1 = m1B[pp];
            ulonglong2 M2 = m2B[pp];
            ulonglong2 Z  = rzB[pp];
            ulonglong2 X  = rxB[pp];
            ulonglong2 R  = r2B[pp];
            u64 t0 = fma2(C1, M1.x, fma2(C2, M2.x, fma2(C3, Z.x, C0)));
            u64 u0 = fma2(E1, X.x,  fma2(E2, R.x,  mul2(E3, Z.x)));
            u64 t1 = fma2(C1, M1.y, fma2(C2, M2.y, fma2(C3, Z.y, C0)));
            u64 u1 = fma2(E1, X.y,  fma2(E2, R.y,  mul2(E3, Z.y)));
            ex2acc(t0, acc0B); ex2acc(t1, acc0B);
            ex2acc(u0, acc1B); ex2acc(u1, acc1B);
        }
    }

    // publish the 64 gib means for both queries
    {
        int qqA = wslot * 2, qqB = qqA + 1;
        meanS[qqA * RPAD + lane]      = acc0A;
        meanS[qqA * RPAD + lane + 32] = acc1A;
        meanS[qqB * RPAD + lane]      = acc0B;
        meanS[qqB * RPAD + lane + 32] = acc1B;
    }
    __syncthreads();

    // ---- block-cooperative epilogue: 16 queries x 16 observers ----
    {
        int qq = tid >> 4;
        int j  = tid & 15;
        const float4* mrow = reinterpret_cast<const float4*>(&meanS[qq * RPAD]);
        float acc = 0.f;
        #pragma unroll
        for (int g4 = 0; g4 < 16; g4++) {
            float4 m = mrow[g4];
            float4 l = lamT4[g4 * 16 + j];
            acc += m.x * l.x + m.y * l.y + m.z * l.z + m.w * l.w;
        }
        out[(size_t)(qbase + qq) * 16 + j] = acc;   // fully coalesced
    }
}

extern "C" void kernel_launch(void* const* d_in, const int* in_sizes, int n_in,
                              void* d_out, int out_size)
{
    // metadata order: points, q_coords, support_idxs, mc_points (unused),
    //                 cy_params, cone_params, disk_params, ellip_params, lambdas
    const float* points       = (const float*)d_in[0];
    const float* q_coords     = (const float*)d_in[1];
    const int*   support_idxs = (const int*)  d_in[2];
    const float* cy_params    = (const float*)d_in[4];
    const float* cone_params  = (const float*)d_in[5];
    const float* disk_params  = (const float*)d_in[6];
    const float* ellip_params = (const float*)d_in[7];
    const float* lambdas      = (const float*)d_in[8];
    float* out = (float*)d_out;

    gib_kernel<<<GRID_BLOCKS, THREADS>>>(points, q_coords, support_idxs,
                                         cy_params, cone_params, disk_params,
                                         ellip_params, lambdas, out);
}